// round 6
// baseline (speedup 1.0000x reference)
#include <cuda_runtime.h>
#include <cuda_bf16.h>
#include <math.h>
#include <stdint.h>

#define Bq 16
#define Tt 1024
#define Dd 512
#define CO 7
#define PRED 96
#define KK 8
#define LATENT 2048
#define NFREQ 511
#define TP (Tt + PRED)

#define RES3_OFF 0
#define LVL_OFF  (Bq*Tt*Dd)
#define GROW_OFF (LVL_OFF + Bq*Tt*CO)
#define SEAS_OFF (GROW_OFF + Bq*(Tt+1)*Dd)

#define PI2 6.283185307179586476925286766559f

// ---------------- scratch ----------------
__device__ float g_Xre[(size_t)Bq*NFREQ*Dd];
__device__ float g_Xim[(size_t)Bq*NFREQ*Dd];
__device__ int   g_fr[Bq*Dd*KK];
__device__ float g_amp[Bq*Dd*KK];
__device__ float g_ph[Bq*Dd*KK];
__device__ float g_res1[(size_t)Bq*Tt*Dd];
__device__ float g_v[(size_t)Bq*Tt*Dd];
__device__ float g_smcat[(size_t)Bq*(Tt+1)*Dd];
__device__ float g_res2[(size_t)Bq*Tt*Dd];
__device__ float g_ffh[(size_t)Bq*Tt*LATENT];
__device__ float g_ffy[(size_t)Bq*Tt*Dd];
__device__ float g_gp[Bq*Tt*CO];
__device__ float g_sp[Bq*Tt*CO];
// DFT twiddle matrix, hi/lo bf16 split: rows 0..511 = cos(f=r+1), 512..1023 = -sin(f=r-511)
__device__ __nv_bfloat16 g_dwh[(size_t)1024*1024];
__device__ __nv_bfloat16 g_dwl[(size_t)1024*1024];
// tf32-prerounded weight buffer (max 2048*512)
__device__ float g_wtf[(size_t)2048*512];

// ---------------- helpers ----------------
__device__ __forceinline__ uint32_t f2tf(float x) {
    uint32_t u;
    asm("cvt.rna.tf32.f32 %0, %1;" : "=r"(u) : "f"(x));
    return u;
}
__device__ __forceinline__ uint32_t packbf(float lo, float hi) {
    uint32_t r;
    asm("cvt.rn.bf16x2.f32 %0, %1, %2;" : "=r"(r) : "f"(hi), "f"(lo));
    return r;
}
__device__ __forceinline__ float bf_round(float x) {
    return __bfloat162float(__float2bfloat16(x));
}
__device__ __forceinline__ void mma_bf16(float* c, const uint32_t* a, const uint32_t* b) {
    asm volatile(
        "mma.sync.aligned.m16n8k16.row.col.f32.bf16.bf16.f32 "
        "{%0,%1,%2,%3}, {%4,%5,%6,%7}, {%8,%9}, {%0,%1,%2,%3};"
        : "+f"(c[0]), "+f"(c[1]), "+f"(c[2]), "+f"(c[3])
        : "r"(a[0]), "r"(a[1]), "r"(a[2]), "r"(a[3]), "r"(b[0]), "r"(b[1]));
}

// ---------------- DFT twiddle precompute ----------------
__global__ void k_dftw() {
    for (int e = blockIdx.x * 256 + threadIdx.x; e < 1024 * 1024; e += 262144) {
        int row = e >> 10, t = e & 1023;
        int f = (row < 512) ? row + 1 : row - 511;
        int ph = (f * t) & 1023;
        float ang = (float)ph * (1.0f / 512.0f);   // units of pi
        float v = (row < 512) ? cospif(ang) : -sinpif(ang);
        float h = bf_round(v);
        g_dwh[e] = __float2bfloat16(h);
        g_dwl[e] = __float2bfloat16(v - h);
    }
}

// ---------------- tensor-core DFT: X[b] = Wtw @ x[b] ----------------
// M=1024 (f rows: cos|sin), N=512 (d), K=1024 (t). split-bf16 3-pass mma.
// BM=BN=128, BK=32, 256 thr (8 warps 2x4), warp tile 64x32.
__device__ __forceinline__ void dft_store(int row, int col, float v0, float v1, int b) {
    if (row < 512) {
        if (row < 511)
            *(float2*)&g_Xre[((size_t)b * NFREQ + row) * Dd + col] = make_float2(v0, v1);
    } else {
        int rr = row - 512;
        if (rr < 511)
            *(float2*)&g_Xim[((size_t)b * NFREQ + rr) * Dd + col] = make_float2(v0, v1);
    }
}

__global__ __launch_bounds__(256)
void k_dftmm(const float* __restrict__ x) {
    extern __shared__ uint32_t ds[];   // 2 stages x (Ah|Al|Bh|Bl) x 2048 words
    int tid = threadIdx.x, lane = tid & 31, warp = tid >> 5;
    int warpM = warp >> 2, warpN = warp & 3;
    int bn = blockIdx.x * 128, bm = blockIdx.y * 128;
    int b = blockIdx.z;
    const float* Bx = x + (size_t)b * Tt * Dd;

    float acc[4][4][4];
#pragma unroll
    for (int i = 0; i < 4; i++)
#pragma unroll
        for (int j = 0; j < 4; j++)
#pragma unroll
            for (int q = 0; q < 4; q++) acc[i][j][q] = 0.f;

    int a_row = tid >> 1, a_half = tid & 1;
    int b_n = tid & 127, b_kg = tid >> 7;
    int Sa = ((a_row >> 1) & 3) << 2;
    int Sb = ((b_n >> 1) & 3) << 2;

    uint4 sa[4];
    float sbv[16];

    // LDG chunk k0 into regs
    auto ldAB = [&](int k0) {
        const uint4* ph = (const uint4*)&g_dwh[((size_t)(bm + a_row)) * 1024 + k0 + a_half * 16];
        const uint4* pl = (const uint4*)&g_dwl[((size_t)(bm + a_row)) * 1024 + k0 + a_half * 16];
        sa[0] = ph[0]; sa[1] = ph[1]; sa[2] = pl[0]; sa[3] = pl[1];
        const float* xp = Bx + (size_t)(k0 + b_kg * 16) * Dd + bn + b_n;
#pragma unroll
        for (int i = 0; i < 16; i++) sbv[i] = xp[(size_t)i * Dd];
    };
    // STS regs into stage s
    auto stAB = [&](int s) {
        uint32_t* Ah = ds + s * 8192;
        uint32_t* Al = Ah + 2048;
        uint32_t* Bh = Ah + 4096;
        uint32_t* Bl = Ah + 6144;
        *(uint4*)&Ah[a_row * 16 + ((a_half * 8 + 0) ^ Sa)] = sa[0];
        *(uint4*)&Ah[a_row * 16 + ((a_half * 8 + 4) ^ Sa)] = sa[1];
        *(uint4*)&Al[a_row * 16 + ((a_half * 8 + 0) ^ Sa)] = sa[2];
        *(uint4*)&Al[a_row * 16 + ((a_half * 8 + 4) ^ Sa)] = sa[3];
#pragma unroll
        for (int i = 0; i < 16; i += 2) {
            float x0 = sbv[i], x1 = sbv[i + 1];
            float h0 = bf_round(x0), h1 = bf_round(x1);
            int w = b_kg * 8 + (i >> 1);
            Bh[b_n * 16 + (w ^ Sb)] = packbf(h0, h1);
            Bl[b_n * 16 + (w ^ Sb)] = packbf(x0 - h0, x1 - h1);
        }
    };

    ldAB(0);
    stAB(0);
    __syncthreads();

    int cq = lane & 3, g = lane >> 2;
    for (int c = 0; c < 32; c++) {
        bool more = c < 31;
        if (more) ldAB((c + 1) * 32);

        int s = c & 1;
        const uint32_t* Ah = ds + s * 8192;
        const uint32_t* Al = Ah + 2048;
        const uint32_t* Bh = Ah + 4096;
        const uint32_t* Bl = Ah + 6144;
#pragma unroll
        for (int ks = 0; ks < 2; ks++) {
            uint32_t ah[4][4], al[4][4], bh[4][2], bl[4][2];
            int w0 = ks * 8 + cq, w4 = ks * 8 + cq + 4;
#pragma unroll
            for (int mt = 0; mt < 4; mt++) {
                int r = warpM * 64 + mt * 16 + g;
                int S = ((r >> 1) & 3) << 2;          // same for r and r+8
                ah[mt][0] = Ah[r * 16 + (w0 ^ S)];
                ah[mt][1] = Ah[(r + 8) * 16 + (w0 ^ S)];
                ah[mt][2] = Ah[r * 16 + (w4 ^ S)];
                ah[mt][3] = Ah[(r + 8) * 16 + (w4 ^ S)];
                al[mt][0] = Al[r * 16 + (w0 ^ S)];
                al[mt][1] = Al[(r + 8) * 16 + (w0 ^ S)];
                al[mt][2] = Al[r * 16 + (w4 ^ S)];
                al[mt][3] = Al[(r + 8) * 16 + (w4 ^ S)];
            }
#pragma unroll
            for (int nt = 0; nt < 4; nt++) {
                int n = warpN * 32 + nt * 8 + g;
                int S = ((n >> 1) & 3) << 2;
                bh[nt][0] = Bh[n * 16 + (w0 ^ S)];
                bh[nt][1] = Bh[n * 16 + (w4 ^ S)];
                bl[nt][0] = Bl[n * 16 + (w0 ^ S)];
                bl[nt][1] = Bl[n * 16 + (w4 ^ S)];
            }
#pragma unroll
            for (int mt = 0; mt < 4; mt++)
#pragma unroll
                for (int nt = 0; nt < 4; nt++) {
                    mma_bf16(acc[mt][nt], ah[mt], bh[nt]);
                    mma_bf16(acc[mt][nt], ah[mt], bl[nt]);
                    mma_bf16(acc[mt][nt], al[mt], bh[nt]);
                }
        }
        if (more) stAB(s ^ 1);
        __syncthreads();
    }

    // epilogue
#pragma unroll
    for (int mt = 0; mt < 4; mt++) {
        int r0 = bm + warpM * 64 + mt * 16 + g;
#pragma unroll
        for (int nt = 0; nt < 4; nt++) {
            int n0 = bn + warpN * 32 + nt * 8 + 2 * cq;
            dft_store(r0,     n0, acc[mt][nt][0], acc[mt][nt][1], b);
            dft_store(r0 + 8, n0, acc[mt][nt][2], acc[mt][nt][3], b);
        }
    }
}

// ---------------- top-K per (b, d) ----------------
__global__ void k_topk() {
    int d = threadIdx.x;
    int b = blockIdx.x;
    float val[KK];
    int   idx[KK];
#pragma unroll
    for (int k = 0; k < KK; k++) { val[k] = -1.f; idx[k] = 0; }

    for (int f = 0; f < NFREQ; f++) {
        size_t o = ((size_t)b * NFREQ + f) * Dd + d;
        float re = g_Xre[o], im = g_Xim[o];
        float m = re * re + im * im;
        if (m > val[KK - 1]) {
            int p = KK - 1;
            while (p > 0 && m > val[p - 1]) {
                val[p] = val[p - 1]; idx[p] = idx[p - 1]; p--;
            }
            val[p] = m; idx[p] = f;
        }
    }
    int base = (b * Dd + d) * KK;
#pragma unroll
    for (int k = 0; k < KK; k++) {
        int f = idx[k];
        size_t o = ((size_t)b * NFREQ + f) * Dd + d;
        float re = g_Xre[o], im = g_Xim[o];
        float mag = sqrtf(re * re + im * im);
        g_fr[base + k]  = f + 1;
        g_amp[base + k] = 2.0f * mag * (1.0f / 1024.0f);
        g_ph[base + k]  = atan2f(im, re);
    }
}

// ---------------- season synthesis + res1 ----------------
__global__ void k_season(const float* __restrict__ res,
                         float* __restrict__ season,
                         float* __restrict__ res1) {
    int d = threadIdx.x;
    int b = blockIdx.y;
    int t0 = blockIdx.x * 16;
    int base = (b * Dd + d) * KK;
    int fr[KK]; float am[KK], ph[KK];
#pragma unroll
    for (int k = 0; k < KK; k++) {
        fr[k] = g_fr[base + k]; am[k] = g_amp[base + k]; ph[k] = g_ph[base + k];
    }
    for (int tt = 0; tt < 16; tt++) {
        int t = t0 + tt;
        float sum = 0.f;
#pragma unroll
        for (int k = 0; k < KK; k++) {
            int id = (fr[k] * t) & 1023;
            sum += am[k] * __cosf((float)id * (PI2 / 1024.0f) + ph[k]);
        }
        season[((size_t)b * TP + t) * Dd + d] = sum;
        if (t < Tt) {
            size_t o = ((size_t)b * Tt + t) * Dd + d;
            res1[o] = res[o] - sum;
        }
    }
}

// ---------------- weight pre-round to tf32 ----------------
__global__ void k_wtf(const float* __restrict__ W, float* __restrict__ O, int n) {
    int i = blockIdx.x * 256 + threadIdx.x;
    if (i < n) O[i] = __uint_as_float(f2tf(W[i]));
}

// ================= tf32 tensor-core GEMM =================
// C[M,N] = A[M,K] @ W[K,N].  W pre-rounded to tf32.  BM=128 BN=128 BK=16,
// 256 threads (8 warps 2x4), warp tile 64x32 of m16n8k8, XOR swizzle, 2-buf.
template <int EPI>
__global__ __launch_bounds__(256)
void k_mma(const float* __restrict__ A, const float* __restrict__ W,
           float* __restrict__ C, int M, int N, int K) {
    const int BM = 128, BN = 128, BK = 16;
    __shared__ uint32_t As[2][BK * BM];
    __shared__ uint32_t Bs[2][BK * BN];

    int tid  = threadIdx.x;
    int lane = tid & 31;
    int warp = tid >> 5;
    int warpM = warp >> 2;
    int warpN = warp & 3;
    int brow = blockIdx.y * BM;
    int bcol = blockIdx.x * BN;

    int lr = lane >> 2;
    int lc = lane & 3;

    float acc[4][4][4];
#pragma unroll
    for (int i = 0; i < 4; i++)
#pragma unroll
        for (int j = 0; j < 4; j++)
#pragma unroll
            for (int q = 0; q < 4; q++) acc[i][j][q] = 0.f;

    int a_m0 = tid >> 2;
    int a_kg = (tid & 3) * 4;
    int b_k0 = tid >> 5;
    int b_n0 = (tid & 31) * 4;

    float4 ra[2], rb[2];

    {
        int k0 = 0;
#pragma unroll
        for (int it = 0; it < 2; it++) {
            int m = a_m0 + it * 64;
            int grow = brow + m;
            float4 v = make_float4(0.f, 0.f, 0.f, 0.f);
            if (grow < M) v = *(const float4*)&A[(size_t)grow * K + k0 + a_kg];
            ra[it] = v;
            int kr = b_k0 + it * 8;
            rb[it] = *(const float4*)&W[(size_t)(k0 + kr) * N + bcol + b_n0];
        }
#pragma unroll
        for (int it = 0; it < 2; it++) {
            int m = a_m0 + it * 64;
            const float* pv = (const float*)&ra[it];
#pragma unroll
            for (int i = 0; i < 4; i++)
                As[0][(a_kg + i) * BM + (m ^ (i << 3))] = f2tf(pv[i]);
            int kr = b_k0 + it * 8;
            int sw = (kr & 3) << 3;
            const float* pw = (const float*)&rb[it];
#pragma unroll
            for (int i = 0; i < 4; i++)
                Bs[0][kr * BN + ((b_n0 + i) ^ sw)] = __float_as_uint(pw[i]);
        }
    }
    __syncthreads();

    int buf = 0;
    for (int k0 = 0; k0 < K; k0 += BK) {
        bool more = (k0 + BK) < K;
        if (more) {
            int kn = k0 + BK;
#pragma unroll
            for (int it = 0; it < 2; it++) {
                int m = a_m0 + it * 64;
                int grow = brow + m;
                float4 v = make_float4(0.f, 0.f, 0.f, 0.f);
                if (grow < M) v = *(const float4*)&A[(size_t)grow * K + kn + a_kg];
                ra[it] = v;
                int kr = b_k0 + it * 8;
                rb[it] = *(const float4*)&W[(size_t)(kn + kr) * N + bcol + b_n0];
            }
        }

        const uint32_t* as = As[buf];
        const uint32_t* bs = Bs[buf];
#pragma unroll
        for (int ks = 0; ks < 2; ks++) {
            uint32_t af[4][4];
#pragma unroll
            for (int mt = 0; mt < 4; mt++) {
                int r = warpM * 64 + mt * 16 + lr;
                int sw = lc << 3;
                af[mt][0] = as[(ks * 8 + lc) * BM + (r ^ sw)];
                af[mt][1] = as[(ks * 8 + lc) * BM + ((r + 8) ^ sw)];
                af[mt][2] = as[(ks * 8 + lc + 4) * BM + (r ^ sw)];
                af[mt][3] = as[(ks * 8 + lc + 4) * BM + ((r + 8) ^ sw)];
            }
            uint32_t bf[4][2];
#pragma unroll
            for (int nt = 0; nt < 4; nt++) {
                int n0 = warpN * 32 + nt * 8 + lr;
                int sw = lc << 3;
                bf[nt][0] = bs[(ks * 8 + lc) * BN + (n0 ^ sw)];
                bf[nt][1] = bs[(ks * 8 + lc + 4) * BN + (n0 ^ sw)];
            }
#pragma unroll
            for (int mt = 0; mt < 4; mt++)
#pragma unroll
                for (int nt = 0; nt < 4; nt++) {
                    asm volatile(
                        "mma.sync.aligned.m16n8k8.row.col.f32.tf32.tf32.f32 "
                        "{%0,%1,%2,%3}, {%4,%5,%6,%7}, {%8,%9}, {%0,%1,%2,%3};"
                        : "+f"(acc[mt][nt][0]), "+f"(acc[mt][nt][1]),
                          "+f"(acc[mt][nt][2]), "+f"(acc[mt][nt][3])
                        : "r"(af[mt][0]), "r"(af[mt][1]), "r"(af[mt][2]), "r"(af[mt][3]),
                          "r"(bf[nt][0]), "r"(bf[nt][1]));
                }
        }

        if (more) {
            int nb = buf ^ 1;
#pragma unroll
            for (int it = 0; it < 2; it++) {
                int m = a_m0 + it * 64;
                const float* pv = (const float*)&ra[it];
#pragma unroll
                for (int i = 0; i < 4; i++)
                    As[nb][(a_kg + i) * BM + (m ^ (i << 3))] = f2tf(pv[i]);
                int kr = b_k0 + it * 8;
                int sw = (kr & 3) << 3;
                const float* pw = (const float*)&rb[it];
#pragma unroll
                for (int i = 0; i < 4; i++)
                    Bs[nb][kr * BN + ((b_n0 + i) ^ sw)] = __float_as_uint(pw[i]);
            }
        }
        __syncthreads();
        buf ^= 1;
    }

#pragma unroll
    for (int mt = 0; mt < 4; mt++) {
        int r0 = brow + warpM * 64 + mt * 16 + lr;
#pragma unroll
        for (int nt = 0; nt < 4; nt++) {
            int col = bcol + warpN * 32 + nt * 8 + 2 * lc;
            float x0 = acc[mt][nt][0], x1 = acc[mt][nt][1];
            float x2 = acc[mt][nt][2], x3 = acc[mt][nt][3];
            if (EPI == 1) {
                x0 = 0.5f * x0 * (1.0f + erff(x0 * 0.70710678118654752440f));
                x1 = 0.5f * x1 * (1.0f + erff(x1 * 0.70710678118654752440f));
                x2 = 0.5f * x2 * (1.0f + erff(x2 * 0.70710678118654752440f));
                x3 = 0.5f * x3 * (1.0f + erff(x3 * 0.70710678118654752440f));
            }
            if (r0 < M)     *(float2*)&C[(size_t)r0 * N + col]       = make_float2(x0, x1);
            if (r0 + 8 < M) *(float2*)&C[(size_t)(r0 + 8) * N + col] = make_float2(x2, x3);
        }
    }
}

// ---------------- growth scan ----------------
__global__ void k_growth_scan(const float* __restrict__ sw,
                              const float* __restrict__ z0,
                              const float* __restrict__ v0) {
    int b = blockIdx.x;
    int hd = threadIdx.x;
    int h = hd >> 6;
    float w = 1.0f / (1.0f + expf(-sw[h]));
    float omw = 1.0f - w;
    float prev = z0[hd];
    float s = v0[hd];
    g_smcat[(size_t)b * (Tt + 1) * Dd + hd] = s;
    const float* vp = g_v + (size_t)b * Tt * Dd + hd;
    float* op = g_smcat + (size_t)b * (Tt + 1) * Dd + Dd + hd;
    for (int t = 0; t < Tt; t++) {
        float val = vp[(size_t)t * Dd];
        float diff = val - prev;
        prev = val;
        s = fmaf(w, s, omw * diff);
        op[(size_t)t * Dd] = s;
    }
}

// ---------------- LayerNorm ----------------
__device__ __forceinline__ float wred(float v) {
#pragma unroll
    for (int o = 16; o > 0; o >>= 1) v += __shfl_xor_sync(0xffffffffu, v, o);
    return v;
}

template <int MODE>
__global__ void k_ln(const float* __restrict__ A, const float* __restrict__ Bm,
                     const float* __restrict__ gg, const float* __restrict__ bb,
                     float* __restrict__ out) {
    int r = blockIdx.x;
    int tid = threadIdx.x;
    const float* arow = A + (size_t)r * Dd;
    const float* brow;
    if (MODE == 0) {
        int b = r >> 10, t = r & 1023;
        brow = Bm + ((size_t)b * (Tt + 1) + t + 1) * Dd;
    } else {
        brow = Bm + (size_t)r * Dd;
    }
    int c0 = tid * 4;
    float4 a = *(const float4*)(arow + c0);
    float4 c = *(const float4*)(brow + c0);
    float x0, x1, x2, x3;
    if (MODE == 0) { x0 = a.x - c.x; x1 = a.y - c.y; x2 = a.z - c.z; x3 = a.w - c.w; }
    else           { x0 = a.x + c.x; x1 = a.y + c.y; x2 = a.z + c.z; x3 = a.w + c.w; }

    __shared__ float red[8];
    float s = x0 + x1 + x2 + x3;
    s = wred(s);
    int wid = tid >> 5, lane = tid & 31;
    if (!lane) red[wid] = s;
    __syncthreads();
    float mu = (red[0] + red[1] + red[2] + red[3]) * (1.0f / 512.0f);
    float d0 = x0 - mu, d1 = x1 - mu, d2 = x2 - mu, d3 = x3 - mu;
    float q = d0 * d0 + d1 * d1 + d2 * d2 + d3 * d3;
    q = wred(q);
    if (!lane) red[4 + wid] = q;
    __syncthreads();
    float var = (red[4] + red[5] + red[6] + red[7]) * (1.0f / 512.0f);
    float inv = rsqrtf(var + 1e-5f);
    float4 g4 = *(const float4*)(gg + c0);
    float4 b4 = *(const float4*)(bb + c0);
    float4 o4;
    o4.x = d0 * inv * g4.x + b4.x;
    o4.y = d1 * inv * g4.y + b4.y;
    o4.z = d2 * inv * g4.z + b4.z;
    o4.w = d3 * inv * g4.w + b4.w;
    *(float4*)(out + (size_t)r * Dd + c0) = o4;
}

// ---------------- small prediction GEMM ----------------
__global__ void k_pred(const float* __restrict__ A, int rows_per_b,
                       const float* __restrict__ W, float* __restrict__ out) {
    __shared__ float ws[Dd * CO];
    int tid = threadIdx.x;
    for (int i = tid; i < Dd * CO; i += 256) ws[i] = W[i];
    __syncthreads();
    int r = blockIdx.x * 256 + tid;
    int b = r >> 10, t = r & 1023;
    const float* a = A + ((size_t)b * rows_per_b + t) * Dd;
    float acc[CO];
#pragma unroll
    for (int c = 0; c < CO; c++) acc[c] = 0.f;
    for (int k = 0; k < Dd; k += 4) {
        float4 av = *(const float4*)(a + k);
#pragma unroll
        for (int c = 0; c < CO; c++) {
            acc[c] = fmaf(av.x, ws[(k + 0) * CO + c], acc[c]);
            acc[c] = fmaf(av.y, ws[(k + 1) * CO + c], acc[c]);
            acc[c] = fmaf(av.z, ws[(k + 2) * CO + c], acc[c]);
            acc[c] = fmaf(av.w, ws[(k + 3) * CO + c], acc[c]);
        }
    }
    float* o = out + (size_t)r * CO;
#pragma unroll
    for (int c = 0; c < CO; c++) o[c] = acc[c];
}

// ---------------- level scan ----------------
__global__ void k_level(const float* __restrict__ level,
                        const float* __restrict__ lsw,
                        const float* __restrict__ lv0,
                        float* __restrict__ out) {
    int tid = threadIdx.x;
    if (tid >= Bq * CO) return;
    int b = tid / CO, c = tid % CO;
    float w = 1.0f / (1.0f + expf(-lsw[c]));
    float omw = 1.0f - w;
    float s = lv0[c];
    float a = 0.f;
    const float* lp = level + (size_t)b * Tt * CO + c;
    const float* gp = g_gp + (size_t)b * Tt * CO + c;
    const float* sp = g_sp + (size_t)b * Tt * CO + c;
    float* op = out + (size_t)b * Tt * CO + c;
    for (int t = 0; t < Tt; t++) {
        float val = lp[t * CO] - sp[t * CO];
        s = fmaf(w, s, omw * val);
        a = w * (a + gp[t * CO]);
        op[t * CO] = s + a;
    }
}

extern "C" void kernel_launch(void* const* d_in, const int* in_sizes, int n_in,
                              void* d_out, int out_size) {
    const float* res   = (const float*)d_in[0];
    const float* level = (const float*)d_in[1];
    const float* in_w  = (const float*)d_in[2];
    const float* out_w = (const float*)d_in[3];
    const float* z0    = (const float*)d_in[4];
    const float* gsw   = (const float*)d_in[5];
    const float* gv0   = (const float*)d_in[6];
    const float* ffw1  = (const float*)d_in[7];
    const float* ffw2  = (const float*)d_in[8];
    const float* n1g   = (const float*)d_in[9];
    const float* n1b   = (const float*)d_in[10];
    const float* n2g   = (const float*)d_in[11];
    const float* n2b   = (const float*)d_in[12];
    const float* gpw   = (const float*)d_in[13];
    const float* spw   = (const float*)d_in[14];
    const float* lsw   = (const float*)d_in[15];
    const float* lv0   = (const float*)d_in[16];
    float* out = (float*)d_out;

    float *p_res1, *p_v, *p_smcat, *p_res2, *p_ffh, *p_ffy, *p_gp, *p_sp, *p_wtf;
    cudaGetSymbolAddress((void**)&p_res1,  g_res1);
    cudaGetSymbolAddress((void**)&p_v,     g_v);
    cudaGetSymbolAddress((void**)&p_smcat, g_smcat);
    cudaGetSymbolAddress((void**)&p_res2,  g_res2);
    cudaGetSymbolAddress((void**)&p_ffh,   g_ffh);
    cudaGetSymbolAddress((void**)&p_ffy,   g_ffy);
    cudaGetSymbolAddress((void**)&p_gp,    g_gp);
    cudaGetSymbolAddress((void**)&p_sp,    g_sp);
    cudaGetSymbolAddress((void**)&p_wtf,   g_wtf);

    cudaFuncSetAttribute(k_dftmm, cudaFuncAttributeMaxDynamicSharedMemorySize, 65536);

    // season path: tensor-core DFT
    k_dftw<<<1024, 256>>>();
    k_dftmm<<<dim3(4, 8, Bq), 256, 65536>>>(res);
    k_topk<<<Bq, 512>>>();
    k_season<<<dim3(TP / 16, Bq), 512>>>(res, out + SEAS_OFF, p_res1);

    // v = res1 @ in_proj_w   [16384,512] x [512,512]
    k_wtf<<<(Dd * Dd + 255) / 256, 256>>>(in_w, p_wtf, Dd * Dd);
    k_mma<0><<<dim3(Dd / 128, Bq * Tt / 128), 256>>>(p_res1, p_wtf, p_v,
                                                     Bq * Tt, Dd, Dd);
    k_growth_scan<<<Bq, 512>>>(gsw, z0, gv0);
    // growth = smcat @ out_proj_w   [16400,512] x [512,512]
    k_wtf<<<(Dd * Dd + 255) / 256, 256>>>(out_w, p_wtf, Dd * Dd);
    k_mma<0><<<dim3(Dd / 128, (Bq * (Tt + 1) + 127) / 128), 256>>>(
        p_smcat, p_wtf, out + GROW_OFF, Bq * (Tt + 1), Dd, Dd);
    k_ln<0><<<Bq * Tt, 128>>>(p_res1, out + GROW_OFF, n1g, n1b, p_res2);
    // ffh = gelu(res2 @ ff_w1)   [16384,512] x [512,2048]
    k_wtf<<<(Dd * LATENT + 255) / 256, 256>>>(ffw1, p_wtf, Dd * LATENT);
    k_mma<1><<<dim3(LATENT / 128, Bq * Tt / 128), 256>>>(
        p_res2, p_wtf, p_ffh, Bq * Tt, LATENT, Dd);
    // ffy = ffh @ ff_w2   [16384,2048] x [2048,512]
    k_wtf<<<(LATENT * Dd + 255) / 256, 256>>>(ffw2, p_wtf, LATENT * Dd);
    k_mma<0><<<dim3(Dd / 128, Bq * Tt / 128), 256>>>(
        p_ffh, p_wtf, p_ffy, Bq * Tt, Dd, LATENT);
    k_ln<1><<<Bq * Tt, 128>>>(p_res2, p_ffy, n2g, n2b, out + RES3_OFF);
    k_pred<<<(Bq * Tt) / 256, 256>>>(out + GROW_OFF, Tt + 1, gpw, p_gp);
    k_pred<<<(Bq * Tt) / 256, 256>>>(out + SEAS_OFF, TP, spw, p_sp);
    k_level<<<1, 128>>>(level, lsw, lv0, out + LVL_OFF);
}

// round 7
// speedup vs baseline: 1.6699x; 1.6699x over previous
#include <cuda_runtime.h>
#include <cuda_bf16.h>
#include <math.h>
#include <stdint.h>

#define Bq 16
#define Tt 1024
#define Dd 512
#define CO 7
#define PRED 96
#define KK 8
#define LATENT 2048
#define NFREQ 511
#define TP (Tt + PRED)

#define RES3_OFF 0
#define LVL_OFF  (Bq*Tt*Dd)
#define GROW_OFF (LVL_OFF + Bq*Tt*CO)
#define SEAS_OFF (GROW_OFF + Bq*(Tt+1)*Dd)

#define PI2 6.283185307179586476925286766559f

// ---------------- scratch ----------------
__device__ float g_Xre[(size_t)Bq*NFREQ*Dd];
__device__ float g_Xim[(size_t)Bq*NFREQ*Dd];
__device__ int   g_fr[Bq*Dd*KK];
__device__ float g_amp[Bq*Dd*KK];
__device__ float g_ph[Bq*Dd*KK];
__device__ float g_res1[(size_t)Bq*Tt*Dd];
__device__ float g_v[(size_t)Bq*Tt*Dd];
__device__ float g_smcat[(size_t)Bq*(Tt+1)*Dd];
__device__ float g_res2[(size_t)Bq*Tt*Dd];
__device__ float g_ffh[(size_t)Bq*Tt*LATENT];
__device__ float g_ffy[(size_t)Bq*Tt*Dd];
__device__ float g_gp[Bq*Tt*CO];
__device__ float g_sp[Bq*Tt*CO];
// DFT twiddle matrix, hi/lo bf16 split
__device__ __nv_bfloat16 g_dwh[(size_t)1024*1024];
__device__ __nv_bfloat16 g_dwl[(size_t)1024*1024];
// tf32-prerounded weight buffer (max 2048*512)
__device__ float g_wtf[(size_t)2048*512];

// ---------------- helpers ----------------
__device__ __forceinline__ uint32_t f2tf(float x) {
    uint32_t u;
    asm("cvt.rna.tf32.f32 %0, %1;" : "=r"(u) : "f"(x));
    return u;
}
__device__ __forceinline__ uint32_t packbf(float lo, float hi) {
    uint32_t r;
    asm("cvt.rn.bf16x2.f32 %0, %1, %2;" : "=r"(r) : "f"(hi), "f"(lo));
    return r;
}
__device__ __forceinline__ float bf_round(float x) {
    return __bfloat162float(__float2bfloat16(x));
}
__device__ __forceinline__ void mma_bf16(float* c, const uint32_t* a, const uint32_t* b) {
    asm volatile(
        "mma.sync.aligned.m16n8k16.row.col.f32.bf16.bf16.f32 "
        "{%0,%1,%2,%3}, {%4,%5,%6,%7}, {%8,%9}, {%0,%1,%2,%3};"
        : "+f"(c[0]), "+f"(c[1]), "+f"(c[2]), "+f"(c[3])
        : "r"(a[0]), "r"(a[1]), "r"(a[2]), "r"(a[3]), "r"(b[0]), "r"(b[1]));
}
__device__ __forceinline__ uint32_t smem_u32(const void* p) {
    uint32_t a;
    asm("{ .reg .u64 t; cvta.to.shared.u64 t, %1; cvt.u32.u64 %0, t; }" : "=r"(a) : "l"(p));
    return a;
}
__device__ __forceinline__ void cp16(uint32_t dst, const void* src, int sz) {
    asm volatile("cp.async.cg.shared.global [%0], [%1], 16, %2;"
                 :: "r"(dst), "l"(src), "r"(sz));
}
#define CP_COMMIT() asm volatile("cp.async.commit_group;")
#define CP_WAIT2()  asm volatile("cp.async.wait_group 2;")

// ---------------- DFT twiddle precompute ----------------
__global__ void k_dftw() {
    for (int e = blockIdx.x * 256 + threadIdx.x; e < 1024 * 1024; e += 262144) {
        int row = e >> 10, t = e & 1023;
        int f = (row < 512) ? row + 1 : row - 511;
        int ph = (f * t) & 1023;
        float ang = (float)ph * (1.0f / 512.0f);
        float v = (row < 512) ? cospif(ang) : -sinpif(ang);
        float h = bf_round(v);
        g_dwh[e] = __float2bfloat16(h);
        g_dwl[e] = __float2bfloat16(v - h);
    }
}

// ---------------- tensor-core DFT (unchanged from round 6) ----------------
__device__ __forceinline__ void dft_store(int row, int col, float v0, float v1, int b) {
    if (row < 512) {
        if (row < 511)
            *(float2*)&g_Xre[((size_t)b * NFREQ + row) * Dd + col] = make_float2(v0, v1);
    } else {
        int rr = row - 512;
        if (rr < 511)
            *(float2*)&g_Xim[((size_t)b * NFREQ + rr) * Dd + col] = make_float2(v0, v1);
    }
}

__global__ __launch_bounds__(256)
void k_dftmm(const float* __restrict__ x) {
    extern __shared__ uint32_t ds[];
    int tid = threadIdx.x, lane = tid & 31, warp = tid >> 5;
    int warpM = warp >> 2, warpN = warp & 3;
    int bn = blockIdx.x * 128, bm = blockIdx.y * 128;
    int b = blockIdx.z;
    const float* Bx = x + (size_t)b * Tt * Dd;

    float acc[4][4][4];
#pragma unroll
    for (int i = 0; i < 4; i++)
#pragma unroll
        for (int j = 0; j < 4; j++)
#pragma unroll
            for (int q = 0; q < 4; q++) acc[i][j][q] = 0.f;

    int a_row = tid >> 1, a_half = tid & 1;
    int b_n = tid & 127, b_kg = tid >> 7;
    int Sa = ((a_row >> 1) & 3) << 2;
    int Sb = ((b_n >> 1) & 3) << 2;

    uint4 sa[4];
    float sbv[16];

    auto ldAB = [&](int k0) {
        const uint4* ph = (const uint4*)&g_dwh[((size_t)(bm + a_row)) * 1024 + k0 + a_half * 16];
        const uint4* pl = (const uint4*)&g_dwl[((size_t)(bm + a_row)) * 1024 + k0 + a_half * 16];
        sa[0] = ph[0]; sa[1] = ph[1]; sa[2] = pl[0]; sa[3] = pl[1];
        const float* xp = Bx + (size_t)(k0 + b_kg * 16) * Dd + bn + b_n;
#pragma unroll
        for (int i = 0; i < 16; i++) sbv[i] = xp[(size_t)i * Dd];
    };
    auto stAB = [&](int s) {
        uint32_t* Ah = ds + s * 8192;
        uint32_t* Al = Ah + 2048;
        uint32_t* Bh = Ah + 4096;
        uint32_t* Bl = Ah + 6144;
        *(uint4*)&Ah[a_row * 16 + ((a_half * 8 + 0) ^ Sa)] = sa[0];
        *(uint4*)&Ah[a_row * 16 + ((a_half * 8 + 4) ^ Sa)] = sa[1];
        *(uint4*)&Al[a_row * 16 + ((a_half * 8 + 0) ^ Sa)] = sa[2];
        *(uint4*)&Al[a_row * 16 + ((a_half * 8 + 4) ^ Sa)] = sa[3];
#pragma unroll
        for (int i = 0; i < 16; i += 2) {
            float x0 = sbv[i], x1 = sbv[i + 1];
            float h0 = bf_round(x0), h1 = bf_round(x1);
            int w = b_kg * 8 + (i >> 1);
            Bh[b_n * 16 + (w ^ Sb)] = packbf(h0, h1);
            Bl[b_n * 16 + (w ^ Sb)] = packbf(x0 - h0, x1 - h1);
        }
    };

    ldAB(0);
    stAB(0);
    __syncthreads();

    int cq = lane & 3, g = lane >> 2;
    for (int c = 0; c < 32; c++) {
        bool more = c < 31;
        if (more) ldAB((c + 1) * 32);

        int s = c & 1;
        const uint32_t* Ah = ds + s * 8192;
        const uint32_t* Al = Ah + 2048;
        const uint32_t* Bh = Ah + 4096;
        const uint32_t* Bl = Ah + 6144;
#pragma unroll
        for (int ks = 0; ks < 2; ks++) {
            uint32_t ah[4][4], al[4][4], bh[4][2], bl[4][2];
            int w0 = ks * 8 + cq, w4 = ks * 8 + cq + 4;
#pragma unroll
            for (int mt = 0; mt < 4; mt++) {
                int r = warpM * 64 + mt * 16 + g;
                int S = ((r >> 1) & 3) << 2;
                ah[mt][0] = Ah[r * 16 + (w0 ^ S)];
                ah[mt][1] = Ah[(r + 8) * 16 + (w0 ^ S)];
                ah[mt][2] = Ah[r * 16 + (w4 ^ S)];
                ah[mt][3] = Ah[(r + 8) * 16 + (w4 ^ S)];
                al[mt][0] = Al[r * 16 + (w0 ^ S)];
                al[mt][1] = Al[(r + 8) * 16 + (w0 ^ S)];
                al[mt][2] = Al[r * 16 + (w4 ^ S)];
                al[mt][3] = Al[(r + 8) * 16 + (w4 ^ S)];
            }
#pragma unroll
            for (int nt = 0; nt < 4; nt++) {
                int n = warpN * 32 + nt * 8 + g;
                int S = ((n >> 1) & 3) << 2;
                bh[nt][0] = Bh[n * 16 + (w0 ^ S)];
                bh[nt][1] = Bh[n * 16 + (w4 ^ S)];
                bl[nt][0] = Bl[n * 16 + (w0 ^ S)];
                bl[nt][1] = Bl[n * 16 + (w4 ^ S)];
            }
#pragma unroll
            for (int mt = 0; mt < 4; mt++)
#pragma unroll
                for (int nt = 0; nt < 4; nt++) {
                    mma_bf16(acc[mt][nt], ah[mt], bh[nt]);
                    mma_bf16(acc[mt][nt], ah[mt], bl[nt]);
                    mma_bf16(acc[mt][nt], al[mt], bh[nt]);
                }
        }
        if (more) stAB(s ^ 1);
        __syncthreads();
    }

#pragma unroll
    for (int mt = 0; mt < 4; mt++) {
        int r0 = bm + warpM * 64 + mt * 16 + g;
#pragma unroll
        for (int nt = 0; nt < 4; nt++) {
            int n0 = bn + warpN * 32 + nt * 8 + 2 * cq;
            dft_store(r0,     n0, acc[mt][nt][0], acc[mt][nt][1], b);
            dft_store(r0 + 8, n0, acc[mt][nt][2], acc[mt][nt][3], b);
        }
    }
}

// ---------------- top-K per (b, d) ----------------
__global__ void k_topk() {
    int d = threadIdx.x;
    int b = blockIdx.x;
    float val[KK];
    int   idx[KK];
#pragma unroll
    for (int k = 0; k < KK; k++) { val[k] = -1.f; idx[k] = 0; }

    for (int f = 0; f < NFREQ; f++) {
        size_t o = ((size_t)b * NFREQ + f) * Dd + d;
        float re = g_Xre[o], im = g_Xim[o];
        float m = re * re + im * im;
        if (m > val[KK - 1]) {
            int p = KK - 1;
            while (p > 0 && m > val[p - 1]) {
                val[p] = val[p - 1]; idx[p] = idx[p - 1]; p--;
            }
            val[p] = m; idx[p] = f;
        }
    }
    int base = (b * Dd + d) * KK;
#pragma unroll
    for (int k = 0; k < KK; k++) {
        int f = idx[k];
        size_t o = ((size_t)b * NFREQ + f) * Dd + d;
        float re = g_Xre[o], im = g_Xim[o];
        float mag = sqrtf(re * re + im * im);
        g_fr[base + k]  = f + 1;
        g_amp[base + k] = 2.0f * mag * (1.0f / 1024.0f);
        g_ph[base + k]  = atan2f(im, re);
    }
}

// ---------------- season synthesis + res1 ----------------
__global__ void k_season(const float* __restrict__ res,
                         float* __restrict__ season,
                         float* __restrict__ res1) {
    int d = threadIdx.x;
    int b = blockIdx.y;
    int t0 = blockIdx.x * 16;
    int base = (b * Dd + d) * KK;
    int fr[KK]; float am[KK], ph[KK];
#pragma unroll
    for (int k = 0; k < KK; k++) {
        fr[k] = g_fr[base + k]; am[k] = g_amp[base + k]; ph[k] = g_ph[base + k];
    }
    for (int tt = 0; tt < 16; tt++) {
        int t = t0 + tt;
        float sum = 0.f;
#pragma unroll
        for (int k = 0; k < KK; k++) {
            int id = (fr[k] * t) & 1023;
            sum += am[k] * __cosf((float)id * (PI2 / 1024.0f) + ph[k]);
        }
        season[((size_t)b * TP + t) * Dd + d] = sum;
        if (t < Tt) {
            size_t o = ((size_t)b * Tt + t) * Dd + d;
            res1[o] = res[o] - sum;
        }
    }
}

// ---------------- weight pre-round to tf32 ----------------
__global__ void k_wtf(const float* __restrict__ W, float* __restrict__ O, int n) {
    int i = blockIdx.x * 256 + threadIdx.x;
    if (i < n) O[i] = __uint_as_float(f2tf(W[i]));
}

// ================= tf32 cp.async multistage GEMM =================
// C[M,N] = A[M,K] @ W[K,N].  W pre-rounded tf32; A raw fp32 (HW-truncated).
// BM=BN=128, BK=16, 4 stages x 16KB, cp.async pipeline, 2 blocks/SM.
// A smem [m][k] swizzle p=k^(((m>>1)&3)<<2); B smem [k][n] swizzle n^((k&3)<<3).
#define GM_SMEM (4 * 16384)

template <int EPI>
__global__ __launch_bounds__(256, 2)
void k_mma(const float* __restrict__ A, const float* __restrict__ W,
           float* __restrict__ C, int M, int N, int K) {
    extern __shared__ uint32_t sm[];
    uint32_t sb = smem_u32(sm);

    int tid  = threadIdx.x;
    int lane = tid & 31;
    int warp = tid >> 5;
    int warpM = warp >> 2;
    int warpN = warp & 3;
    int brow = blockIdx.y * 128;
    int bcol = blockIdx.x * 128;
    int lr = lane >> 2;
    int lc = lane & 3;

    float acc[4][4][4];
#pragma unroll
    for (int i = 0; i < 4; i++)
#pragma unroll
        for (int j = 0; j < 4; j++)
#pragma unroll
            for (int q = 0; q < 4; q++) acc[i][j][q] = 0.f;

    // cp.async thread mapping
    int am  = tid >> 1;                  // A row 0..127
    int akg = (tid & 1) * 2;             // A k-groups akg, akg+1 (of 4)
    int asz = (brow + am < M) ? 16 : 0;
    const float* a_base = A + (size_t)(brow + am) * K;
    uint32_t a_off0 = (uint32_t)(am * 16 + (((akg + 0) * 4) ^ (((am >> 1) & 3) << 2))) * 4;
    uint32_t a_off1 = (uint32_t)(am * 16 + (((akg + 1) * 4) ^ (((am >> 1) & 3) << 2))) * 4;

    int bkr = tid >> 4;                  // B k-row 0..15
    int bn4 = (tid & 15) * 2;            // B n-chunks bn4, bn4+1 (of 32)
    const float* b_base = W + (size_t)bkr * N + bcol;
    uint32_t b_off0 = (uint32_t)(8192 + (bkr * 128 + (((bn4 + 0) * 4) ^ ((bkr & 3) << 3))) * 4);
    uint32_t b_off1 = (uint32_t)(8192 + (bkr * 128 + (((bn4 + 1) * 4) ^ ((bkr & 3) << 3))) * 4);

    const int NC = K >> 4;

    auto issue = [&](int c) {
        uint32_t base = sb + (uint32_t)(c & 3) * 16384;
        int k0 = c * 16;
        cp16(base + a_off0, a_base + k0 + (akg + 0) * 4, asz);
        cp16(base + a_off1, a_base + k0 + (akg + 1) * 4, asz);
        cp16(base + b_off0, b_base + (size_t)k0 * N + (bn4 + 0) * 4, 16);
        cp16(base + b_off1, b_base + (size_t)k0 * N + (bn4 + 1) * 4, 16);
    };

    issue(0); CP_COMMIT();
    issue(1); CP_COMMIT();
    issue(2); CP_COMMIT();

    for (int c = 0; c < NC; c++) {
        CP_WAIT2();
        __syncthreads();
        if (c + 3 < NC) issue(c + 3);
        CP_COMMIT();

        const uint32_t* as = sm + (size_t)(c & 3) * 4096;
        const uint32_t* bs = as + 2048;
#pragma unroll
        for (int ks = 0; ks < 2; ks++) {
            int w0 = ks * 8 + lc, w4 = w0 + 4;
            uint32_t af[4][4];
#pragma unroll
            for (int mt = 0; mt < 4; mt++) {
                int r = warpM * 64 + mt * 16 + lr;
                int S = ((r >> 1) & 3) << 2;
                af[mt][0] = as[r * 16 + (w0 ^ S)];
                af[mt][1] = as[(r + 8) * 16 + (w0 ^ S)];
                af[mt][2] = as[r * 16 + (w4 ^ S)];
                af[mt][3] = as[(r + 8) * 16 + (w4 ^ S)];
            }
            uint32_t bf[4][2];
#pragma unroll
            for (int nt = 0; nt < 4; nt++) {
                int n0 = warpN * 32 + nt * 8 + lr;
                int X = lc << 3;
                bf[nt][0] = bs[w0 * 128 + (n0 ^ X)];
                bf[nt][1] = bs[w4 * 128 + (n0 ^ X)];
            }
#pragma unroll
            for (int mt = 0; mt < 4; mt++)
#pragma unroll
                for (int nt = 0; nt < 4; nt++) {
                    asm volatile(
                        "mma.sync.aligned.m16n8k8.row.col.f32.tf32.tf32.f32 "
                        "{%0,%1,%2,%3}, {%4,%5,%6,%7}, {%8,%9}, {%0,%1,%2,%3};"
                        : "+f"(acc[mt][nt][0]), "+f"(acc[mt][nt][1]),
                          "+f"(acc[mt][nt][2]), "+f"(acc[mt][nt][3])
                        : "r"(af[mt][0]), "r"(af[mt][1]), "r"(af[mt][2]), "r"(af[mt][3]),
                          "r"(bf[nt][0]), "r"(bf[nt][1]));
                }
        }
        __syncthreads();
    }

#pragma unroll
    for (int mt = 0; mt < 4; mt++) {
        int r0 = brow + warpM * 64 + mt * 16 + lr;
#pragma unroll
        for (int nt = 0; nt < 4; nt++) {
            int col = bcol + warpN * 32 + nt * 8 + 2 * lc;
            float x0 = acc[mt][nt][0], x1 = acc[mt][nt][1];
            float x2 = acc[mt][nt][2], x3 = acc[mt][nt][3];
            if (EPI == 1) {
                x0 = 0.5f * x0 * (1.0f + erff(x0 * 0.70710678118654752440f));
                x1 = 0.5f * x1 * (1.0f + erff(x1 * 0.70710678118654752440f));
                x2 = 0.5f * x2 * (1.0f + erff(x2 * 0.70710678118654752440f));
                x3 = 0.5f * x3 * (1.0f + erff(x3 * 0.70710678118654752440f));
            }
            if (r0 < M)     *(float2*)&C[(size_t)r0 * N + col]       = make_float2(x0, x1);
            if (r0 + 8 < M) *(float2*)&C[(size_t)(r0 + 8) * N + col] = make_float2(x2, x3);
        }
    }
}

// ---------------- growth scan ----------------
__global__ void k_growth_scan(const float* __restrict__ sw,
                              const float* __restrict__ z0,
                              const float* __restrict__ v0) {
    int b = blockIdx.x;
    int hd = threadIdx.x;
    int h = hd >> 6;
    float w = 1.0f / (1.0f + expf(-sw[h]));
    float omw = 1.0f - w;
    float prev = z0[hd];
    float s = v0[hd];
    g_smcat[(size_t)b * (Tt + 1) * Dd + hd] = s;
    const float* vp = g_v + (size_t)b * Tt * Dd + hd;
    float* op = g_smcat + (size_t)b * (Tt + 1) * Dd + Dd + hd;
    for (int t = 0; t < Tt; t++) {
        float val = vp[(size_t)t * Dd];
        float diff = val - prev;
        prev = val;
        s = fmaf(w, s, omw * diff);
        op[(size_t)t * Dd] = s;
    }
}

// ---------------- LayerNorm ----------------
__device__ __forceinline__ float wred(float v) {
#pragma unroll
    for (int o = 16; o > 0; o >>= 1) v += __shfl_xor_sync(0xffffffffu, v, o);
    return v;
}

template <int MODE>
__global__ void k_ln(const float* __restrict__ A, const float* __restrict__ Bm,
                     const float* __restrict__ gg, const float* __restrict__ bb,
                     float* __restrict__ out) {
    int r = blockIdx.x;
    int tid = threadIdx.x;
    const float* arow = A + (size_t)r * Dd;
    const float* brow;
    if (MODE == 0) {
        int b = r >> 10, t = r & 1023;
        brow = Bm + ((size_t)b * (Tt + 1) + t + 1) * Dd;
    } else {
        brow = Bm + (size_t)r * Dd;
    }
    int c0 = tid * 4;
    float4 a = *(const float4*)(arow + c0);
    float4 c = *(const float4*)(brow + c0);
    float x0, x1, x2, x3;
    if (MODE == 0) { x0 = a.x - c.x; x1 = a.y - c.y; x2 = a.z - c.z; x3 = a.w - c.w; }
    else           { x0 = a.x + c.x; x1 = a.y + c.y; x2 = a.z + c.z; x3 = a.w + c.w; }

    __shared__ float red[8];
    float s = x0 + x1 + x2 + x3;
    s = wred(s);
    int wid = tid >> 5, lane = tid & 31;
    if (!lane) red[wid] = s;
    __syncthreads();
    float mu = (red[0] + red[1] + red[2] + red[3]) * (1.0f / 512.0f);
    float d0 = x0 - mu, d1 = x1 - mu, d2 = x2 - mu, d3 = x3 - mu;
    float q = d0 * d0 + d1 * d1 + d2 * d2 + d3 * d3;
    q = wred(q);
    if (!lane) red[4 + wid] = q;
    __syncthreads();
    float var = (red[4] + red[5] + red[6] + red[7]) * (1.0f / 512.0f);
    float inv = rsqrtf(var + 1e-5f);
    float4 g4 = *(const float4*)(gg + c0);
    float4 b4 = *(const float4*)(bb + c0);
    float4 o4;
    o4.x = d0 * inv * g4.x + b4.x;
    o4.y = d1 * inv * g4.y + b4.y;
    o4.z = d2 * inv * g4.z + b4.z;
    o4.w = d3 * inv * g4.w + b4.w;
    *(float4*)(out + (size_t)r * Dd + c0) = o4;
}

// ---------------- small prediction GEMM ----------------
__global__ void k_pred(const float* __restrict__ A, int rows_per_b,
                       const float* __restrict__ W, float* __restrict__ out) {
    __shared__ float ws[Dd * CO];
    int tid = threadIdx.x;
    for (int i = tid; i < Dd * CO; i += 256) ws[i] = W[i];
    __syncthreads();
    int r = blockIdx.x * 256 + tid;
    int b = r >> 10, t = r & 1023;
    const float* a = A + ((size_t)b * rows_per_b + t) * Dd;
    float acc[CO];
#pragma unroll
    for (int c = 0; c < CO; c++) acc[c] = 0.f;
    for (int k = 0; k < Dd; k += 4) {
        float4 av = *(const float4*)(a + k);
#pragma unroll
        for (int c = 0; c < CO; c++) {
            acc[c] = fmaf(av.x, ws[(k + 0) * CO + c], acc[c]);
            acc[c] = fmaf(av.y, ws[(k + 1) * CO + c], acc[c]);
            acc[c] = fmaf(av.z, ws[(k + 2) * CO + c], acc[c]);
            acc[c] = fmaf(av.w, ws[(k + 3) * CO + c], acc[c]);
        }
    }
    float* o = out + (size_t)r * CO;
#pragma unroll
    for (int c = 0; c < CO; c++) o[c] = acc[c];
}

// ---------------- level scan ----------------
__global__ void k_level(const float* __restrict__ level,
                        const float* __restrict__ lsw,
                        const float* __restrict__ lv0,
                        float* __restrict__ out) {
    int tid = threadIdx.x;
    if (tid >= Bq * CO) return;
    int b = tid / CO, c = tid % CO;
    float w = 1.0f / (1.0f + expf(-lsw[c]));
    float omw = 1.0f - w;
    float s = lv0[c];
    float a = 0.f;
    const float* lp = level + (size_t)b * Tt * CO + c;
    const float* gp = g_gp + (size_t)b * Tt * CO + c;
    const float* sp = g_sp + (size_t)b * Tt * CO + c;
    float* op = out + (size_t)b * Tt * CO + c;
    for (int t = 0; t < Tt; t++) {
        float val = lp[t * CO] - sp[t * CO];
        s = fmaf(w, s, omw * val);
        a = w * (a + gp[t * CO]);
        op[t * CO] = s + a;
    }
}

extern "C" void kernel_launch(void* const* d_in, const int* in_sizes, int n_in,
                              void* d_out, int out_size) {
    const float* res   = (const float*)d_in[0];
    const float* level = (const float*)d_in[1];
    const float* in_w  = (const float*)d_in[2];
    const float* out_w = (const float*)d_in[3];
    const float* z0    = (const float*)d_in[4];
    const float* gsw   = (const float*)d_in[5];
    const float* gv0   = (const float*)d_in[6];
    const float* ffw1  = (const float*)d_in[7];
    const float* ffw2  = (const float*)d_in[8];
    const float* n1g   = (const float*)d_in[9];
    const float* n1b   = (const float*)d_in[10];
    const float* n2g   = (const float*)d_in[11];
    const float* n2b   = (const float*)d_in[12];
    const float* gpw   = (const float*)d_in[13];
    const float* spw   = (const float*)d_in[14];
    const float* lsw   = (const float*)d_in[15];
    const float* lv0   = (const float*)d_in[16];
    float* out = (float*)d_out;

    float *p_res1, *p_v, *p_smcat, *p_res2, *p_ffh, *p_ffy, *p_gp, *p_sp, *p_wtf;
    cudaGetSymbolAddress((void**)&p_res1,  g_res1);
    cudaGetSymbolAddress((void**)&p_v,     g_v);
    cudaGetSymbolAddress((void**)&p_smcat, g_smcat);
    cudaGetSymbolAddress((void**)&p_res2,  g_res2);
    cudaGetSymbolAddress((void**)&p_ffh,   g_ffh);
    cudaGetSymbolAddress((void**)&p_ffy,   g_ffy);
    cudaGetSymbolAddress((void**)&p_gp,    g_gp);
    cudaGetSymbolAddress((void**)&p_sp,    g_sp);
    cudaGetSymbolAddress((void**)&p_wtf,   g_wtf);

    cudaFuncSetAttribute(k_dftmm, cudaFuncAttributeMaxDynamicSharedMemorySize, 65536);
    cudaFuncSetAttribute(k_mma<0>, cudaFuncAttributeMaxDynamicSharedMemorySize, GM_SMEM);
    cudaFuncSetAttribute(k_mma<1>, cudaFuncAttributeMaxDynamicSharedMemorySize, GM_SMEM);

    // season path: tensor-core DFT
    k_dftw<<<1024, 256>>>();
    k_dftmm<<<dim3(4, 8, Bq), 256, 65536>>>(res);
    k_topk<<<Bq, 512>>>();
    k_season<<<dim3(TP / 16, Bq), 512>>>(res, out + SEAS_OFF, p_res1);

    // v = res1 @ in_proj_w   [16384,512] x [512,512]
    k_wtf<<<(Dd * Dd + 255) / 256, 256>>>(in_w, p_wtf, Dd * Dd);
    k_mma<0><<<dim3(Dd / 128, Bq * Tt / 128), 256, GM_SMEM>>>(p_res1, p_wtf, p_v,
                                                              Bq * Tt, Dd, Dd);
    k_growth_scan<<<Bq, 512>>>(gsw, z0, gv0);
    // growth = smcat @ out_proj_w   [16400,512] x [512,512]
    k_wtf<<<(Dd * Dd + 255) / 256, 256>>>(out_w, p_wtf, Dd * Dd);
    k_mma<0><<<dim3(Dd / 128, (Bq * (Tt + 1) + 127) / 128), 256, GM_SMEM>>>(
        p_smcat, p_wtf, out + GROW_OFF, Bq * (Tt + 1), Dd, Dd);
    k_ln<0><<<Bq * Tt, 128>>>(p_res1, out + GROW_OFF, n1g, n1b, p_res2);
    // ffh = gelu(res2 @ ff_w1)   [16384,512] x [512,2048]
    k_wtf<<<(Dd * LATENT + 255) / 256, 256>>>(ffw1, p_wtf, Dd * LATENT);
    k_mma<1><<<dim3(LATENT / 128, Bq * Tt / 128), 256, GM_SMEM>>>(
        p_res2, p_wtf, p_ffh, Bq * Tt, LATENT, Dd);
    // ffy = ffh @ ff_w2   [16384,2048] x [2048,512]
    k_wtf<<<(LATENT * Dd + 255) / 256, 256>>>(ffw2, p_wtf, LATENT * Dd);
    k_mma<0><<<dim3(Dd / 128, Bq * Tt / 128), 256, GM_SMEM>>>(
        p_ffh, p_wtf, p_ffy, Bq * Tt, Dd, LATENT);
    k_ln<1><<<Bq * Tt, 128>>>(p_res2, p_ffy, n2g, n2b, out + RES3_OFF);
    k_pred<<<(Bq * Tt) / 256, 256>>>(out + GROW_OFF, Tt + 1, gpw, p_gp);
    k_pred<<<(Bq * Tt) / 256, 256>>>(out + SEAS_OFF, TP, spw, p_sp);
    k_level<<<1, 128>>>(level, lsw, lv0, out + LVL_OFF);
}